// round 17
// baseline (speedup 1.0000x reference)
#include <cuda_runtime.h>
#include <cuda_fp16.h>
#include <mma.h>
#include <math.h>

using namespace nvcuda;

#define NMAX 50000
#define EMAX 800000
#define DMAX 128

// Scratch (device globals; no allocation in kernel_launch)
__device__ __half g_hs[NMAX * DMAX];   // h (= x@W)*dis payload in fp16
__device__ __half g_xh[NMAX * DMAX];   // layer activations (fp16)
__device__ float g_dis[NMAX];          // rsqrt(deg+1)
__device__ float g_s[NMAX];            // node scores
__device__ int   g_counts[NMAX];       // in-degree histogram
__device__ int   g_offsets[NMAX + 1];  // CSR row offsets
__device__ int   g_cursor[NMAX];       // fill cursors
__device__ int   g_csr[EMAX];          // CSR src indices grouped by dst

// ---------------------------------------------------------------------------
// Histogram, 4 edges per thread (int4)
__global__ void hist_kernel(const int* __restrict__ dst, int E, int* counts) {
    int i = blockIdx.x * blockDim.x + threadIdx.x;
    int E4 = E >> 2;
    if (i < E4) {
        int4 d = ((const int4*)dst)[i];
        atomicAdd(&counts[d.x], 1);
        atomicAdd(&counts[d.y], 1);
        atomicAdd(&counts[d.z], 1);
        atomicAdd(&counts[d.w], 1);
    }
    int t = E4 * 4 + i;
    if (i < (E & 3)) atomicAdd(&counts[dst[t]], 1);
}

// Single-block fused exclusive scan (warp shuffles, int4 tiles of 4096).
// Produces offsets, cursor, dis in one launch.
__global__ void scan_fused_kernel(const int* __restrict__ counts,
                                  int* __restrict__ offsets,
                                  int* __restrict__ cursor,
                                  float* __restrict__ dis, int n) {
    __shared__ int warp_sums[32];
    int t = threadIdx.x;
    int lane = t & 31, wid = t >> 5;
    int carry = 0;

    for (int base = 0; base < n; base += 4096) {
        int i = base + t * 4;
        int4 c = make_int4(0, 0, 0, 0);
        if (i + 3 < n) {
            c = *(const int4*)&counts[i];
        } else {
            if (i < n) c.x = counts[i];
            if (i + 1 < n) c.y = counts[i + 1];
            if (i + 2 < n) c.z = counts[i + 2];
            if (i + 3 < n) c.w = counts[i + 3];
        }
        int s0 = c.x, s1 = s0 + c.y, s2 = s1 + c.z, s3 = s2 + c.w;
        int tsum = s3;

        // warp inclusive scan of per-thread sums
        int v = tsum;
#pragma unroll
        for (int o = 1; o < 32; o <<= 1) {
            int u = __shfl_up_sync(0xffffffffu, v, o);
            if (lane >= o) v += u;
        }
        if (lane == 31) warp_sums[wid] = v;
        __syncthreads();
        if (wid == 0) {
            int w = warp_sums[lane];
#pragma unroll
            for (int o = 1; o < 32; o <<= 1) {
                int u = __shfl_up_sync(0xffffffffu, w, o);
                if (lane >= o) w += u;
            }
            warp_sums[lane] = w;
        }
        __syncthreads();
        int warp_excl = (wid == 0) ? 0 : warp_sums[wid - 1];
        int tile_total = warp_sums[31];
        int te = carry + warp_excl + (v - tsum);  // exclusive at thread start

        if (i + 3 < n) {
            int4 o4 = make_int4(te, te + s0, te + s1, te + s2);
            *(int4*)&offsets[i] = o4;
            *(int4*)&cursor[i] = o4;
            float4 d4 = make_float4(rsqrtf((float)c.x + 1.0f),
                                    rsqrtf((float)c.y + 1.0f),
                                    rsqrtf((float)c.z + 1.0f),
                                    rsqrtf((float)c.w + 1.0f));
            *(float4*)&dis[i] = d4;
        } else {
            int os[4] = {te, te + s0, te + s1, te + s2};
            int cs[4] = {c.x, c.y, c.z, c.w};
            for (int j = 0; j < 4; j++) {
                if (i + j < n) {
                    offsets[i + j] = os[j];
                    cursor[i + j] = os[j];
                    dis[i + j] = rsqrtf((float)cs[j] + 1.0f);
                }
            }
        }
        carry += tile_total;
        __syncthreads();  // protect warp_sums for next tile
    }
    if (t == 0) offsets[n] = carry;
}

// CSR fill, 4 edges per thread
__global__ void fill_kernel(const int* __restrict__ src,
                            const int* __restrict__ dst, int E,
                            int* cursor, int* __restrict__ csr) {
    int i = blockIdx.x * blockDim.x + threadIdx.x;
    int E4 = E >> 2;
    if (i < E4) {
        int4 s = ((const int4*)src)[i];
        int4 d = ((const int4*)dst)[i];
        int p0 = atomicAdd(&cursor[d.x], 1);
        int p1 = atomicAdd(&cursor[d.y], 1);
        int p2 = atomicAdd(&cursor[d.z], 1);
        int p3 = atomicAdd(&cursor[d.w], 1);
        csr[p0] = s.x;
        csr[p1] = s.y;
        csr[p2] = s.z;
        csr[p3] = s.w;
    }
    int t = E4 * 4 + i;
    if (i < (E & 3)) {
        int pos = atomicAdd(&cursor[dst[t]], 1);
        csr[pos] = src[t];
    }
}

// ---------------------------------------------------------------------------
// Tensor-core GEMM (wmma / HMMA, fp16 in, fp32 accumulate) + row scale.
// out[r, c] = half((A@W)[r, c] * dis[r]).  BM=64 rows/block, 256 threads.
template <int DIN, int DOUT, typename AT>
__global__ void __launch_bounds__(256)
wmma_gemm_kernel(const AT* __restrict__ A, const float* __restrict__ W,
                 const float* __restrict__ dis, __half* __restrict__ out, int n) {
    constexpr int BM = 64;
    constexpr int WARPS_N = (DOUT == 128) ? 4 : 2;
    constexpr int WARPS_M = 8 / WARPS_N;
    constexpr int WM = BM / WARPS_M;
    constexpr int WN = DOUT / WARPS_N;
    constexpr int MF = WM / 16;
    constexpr int NF = WN / 16;

    __shared__ __half As[BM * 16];
    __shared__ __half Ws[16 * DOUT];
    __shared__ float  Cs[BM * DOUT];

    int tid = threadIdx.x;
    int wid = tid >> 5;
    int wm = wid / WARPS_N, wn = wid % WARPS_N;
    int row0 = blockIdx.x * BM;

    wmma::fragment<wmma::accumulator, 16, 16, 16, float> cf[MF][NF];
#pragma unroll
    for (int mf = 0; mf < MF; mf++)
#pragma unroll
        for (int nf = 0; nf < NF; nf++) wmma::fill_fragment(cf[mf][nf], 0.0f);

    for (int k0 = 0; k0 < DIN; k0 += 16) {
        {
            int r = tid >> 2;
            int c = (tid & 3) * 4;
            int gr = row0 + r;
            __half h[4];
            if (gr < n) {
                if constexpr (sizeof(AT) == 4) {
                    float4 v = *(const float4*)&A[(size_t)gr * DIN + k0 + c];
                    h[0] = __float2half_rn(v.x);
                    h[1] = __float2half_rn(v.y);
                    h[2] = __float2half_rn(v.z);
                    h[3] = __float2half_rn(v.w);
                } else {
                    uint2 v = *(const uint2*)&A[(size_t)gr * DIN + k0 + c];
                    *(uint2*)h = v;
                }
            } else {
                h[0] = h[1] = h[2] = h[3] = __ushort_as_half(0);
            }
            *(uint2*)&As[r * 16 + c] = *(uint2*)h;
        }
        for (int i = tid * 4; i < 16 * DOUT; i += 256 * 4) {
            int kr = i / DOUT, c = i % DOUT;
            float4 v = *(const float4*)&W[(size_t)(k0 + kr) * DOUT + c];
            __half h[4] = {__float2half_rn(v.x), __float2half_rn(v.y),
                           __float2half_rn(v.z), __float2half_rn(v.w)};
            *(uint2*)&Ws[i] = *(uint2*)h;
        }
        __syncthreads();

        wmma::fragment<wmma::matrix_a, 16, 16, 16, __half, wmma::row_major> af[MF];
        wmma::fragment<wmma::matrix_b, 16, 16, 16, __half, wmma::row_major> bf[NF];
#pragma unroll
        for (int mf = 0; mf < MF; mf++)
            wmma::load_matrix_sync(af[mf], &As[(wm * WM + mf * 16) * 16], 16);
#pragma unroll
        for (int nf = 0; nf < NF; nf++)
            wmma::load_matrix_sync(bf[nf], &Ws[wn * WN + nf * 16], DOUT);
#pragma unroll
        for (int mf = 0; mf < MF; mf++)
#pragma unroll
            for (int nf = 0; nf < NF; nf++)
                wmma::mma_sync(cf[mf][nf], af[mf], bf[nf], cf[mf][nf]);
        __syncthreads();
    }

#pragma unroll
    for (int mf = 0; mf < MF; mf++)
#pragma unroll
        for (int nf = 0; nf < NF; nf++)
            wmma::store_matrix_sync(
                &Cs[(wm * WM + mf * 16) * DOUT + wn * WN + nf * 16],
                cf[mf][nf], DOUT, wmma::mem_row_major);
    __syncthreads();

    for (int i = tid * 4; i < BM * DOUT; i += 256 * 4) {
        int r = i / DOUT, c = i % DOUT;
        int gr = row0 + r;
        if (gr < n) {
            float dv = dis[gr];
            float4 v = *(const float4*)&Cs[i];
            __half2 h0 = __float22half2_rn(make_float2(v.x * dv, v.y * dv));
            __half2 h1 = __float22half2_rn(make_float2(v.z * dv, v.w * dv));
            uint2 pk = make_uint2(*(unsigned*)&h0, *(unsigned*)&h1);
            *(uint2*)&out[(size_t)gr * DOUT + c] = pk;
        }
    }
}

// ---------------------------------------------------------------------------
// fp16 vector loads, fp32 accumulate.
template <int VW>
__device__ __forceinline__ void vload_add_h(const __half* __restrict__ p, float* a) {
    if constexpr (VW == 4) {
        uint2 u = *(const uint2*)p;
        float2 f0 = __half22float2(*(const __half2*)&u.x);
        float2 f1 = __half22float2(*(const __half2*)&u.y);
        a[0] += f0.x; a[1] += f0.y; a[2] += f1.x; a[3] += f1.y;
    } else if constexpr (VW == 2) {
        __half2 h = *(const __half2*)p;
        float2 f = __half22float2(h);
        a[0] += f.x; a[1] += f.y;
    } else {
        a[0] += __half2float(*p);
    }
}
template <int VW>
__device__ __forceinline__ void vstore_h(__half* __restrict__ p, const float* r) {
    if constexpr (VW == 4) {
        __half2 h0 = __float22half2_rn(make_float2(r[0], r[1]));
        __half2 h1 = __float22half2_rn(make_float2(r[2], r[3]));
        uint2 pk = make_uint2(*(unsigned*)&h0, *(unsigned*)&h1);
        *(uint2*)p = pk;
    } else if constexpr (VW == 2) {
        *(__half2*)p = __float22half2_rn(make_float2(r[0], r[1]));
    } else {
        *p = __float2half_rn(r[0]);
    }
}

// Core gather loop: acc += hs rows for csr[s0..s1), int4 index loads.
// hs rows are pre-scaled by dis[row].
template <int VW>
__device__ __forceinline__ void gather_rows(const __half* __restrict__ base,
                                            const int* __restrict__ csr,
                                            int s0, int s1,
                                            float* a0, float* a1,
                                            float* a2, float* a3) {
    constexpr int DOUT = VW * 32;
    int e = s0;
    // lead-in to 4-edge alignment
    while (e < s1 && (e & 3)) {
        int i0 = __ldg(&csr[e]);
        vload_add_h<VW>(base + (size_t)i0 * DOUT, a0);
        e++;
    }
    for (; e + 8 <= s1; e += 8) {
        int4 q0 = __ldg((const int4*)&csr[e]);
        int4 q1 = __ldg((const int4*)&csr[e + 4]);
        vload_add_h<VW>(base + (size_t)q0.x * DOUT, a0);
        vload_add_h<VW>(base + (size_t)q0.y * DOUT, a1);
        vload_add_h<VW>(base + (size_t)q0.z * DOUT, a2);
        vload_add_h<VW>(base + (size_t)q0.w * DOUT, a3);
        vload_add_h<VW>(base + (size_t)q1.x * DOUT, a0);
        vload_add_h<VW>(base + (size_t)q1.y * DOUT, a1);
        vload_add_h<VW>(base + (size_t)q1.z * DOUT, a2);
        vload_add_h<VW>(base + (size_t)q1.w * DOUT, a3);
    }
    if (e + 4 <= s1) {
        int4 q0 = __ldg((const int4*)&csr[e]);
        vload_add_h<VW>(base + (size_t)q0.x * DOUT, a0);
        vload_add_h<VW>(base + (size_t)q0.y * DOUT, a1);
        vload_add_h<VW>(base + (size_t)q0.z * DOUT, a2);
        vload_add_h<VW>(base + (size_t)q0.w * DOUT, a3);
        e += 4;
    }
    while (e < s1) {
        int i0 = __ldg(&csr[e]);
        vload_add_h<VW>(base + (size_t)i0 * DOUT, a0);
        e++;
    }
}

// One warp per node: out = relu(dis[v]*(acc + hs[v]) + b), fp16 out.
template <int DOUT>
__global__ void __launch_bounds__(256)
gather_combine_kernel(const __half* __restrict__ hs,
                      const int* __restrict__ csr,
                      const int* __restrict__ offsets,
                      const float* __restrict__ b,
                      const float* __restrict__ dis,
                      __half* __restrict__ out, int n) {
    constexpr int VW = DOUT / 32;
    int warp = (blockIdx.x * blockDim.x + threadIdx.x) >> 5;
    int lane = threadIdx.x & 31;
    if (warp >= n) return;
    int v = warp;
    int s0 = offsets[v], s1 = offsets[v + 1];

    float a0[VW] = {}, a1[VW] = {}, a2[VW] = {}, a3[VW] = {};
    int fo = lane * VW;
    const __half* __restrict__ base = hs + fo;

    gather_rows<VW>(base, csr, s0, s1, a0, a1, a2, a3);

    float dv = dis[v];
    const __half* hp = hs + (size_t)v * DOUT + fo;
    __half* op = out + (size_t)v * DOUT + fo;

    float self[VW] = {};
    vload_add_h<VW>(hp, self);

    float r[VW];
#pragma unroll
    for (int j = 0; j < VW; j++) {
        float t = dv * ((a0[j] + a1[j]) + (a2[j] + a3[j]) + self[j]) + b[fo + j];
        r[j] = t > 0.0f ? t : 0.0f;
    }
    vstore_h<VW>(op, r);
}

// ---------------------------------------------------------------------------
// Layer-2 gather (DOUT=32, VW=1) fused with the MLP head:
// x(32) -> relu(16) -> relu(8) -> sigmoid(1), in-warp via shuffles.
__global__ void __launch_bounds__(256)
gather_combine_mlp_kernel(const __half* __restrict__ hs,
                          const int* __restrict__ csr,
                          const int* __restrict__ offsets,
                          const float* __restrict__ b,
                          const float* __restrict__ dis,
                          const float* __restrict__ lw0, const float* __restrict__ lb0,
                          const float* __restrict__ lw1, const float* __restrict__ lb1,
                          const float* __restrict__ lw2, const float* __restrict__ lb2,
                          float* __restrict__ s, int n) {
    __shared__ float w0[32 * 16], b0s[16], w1[16 * 8], b1s[8], w2s[8], b2s[1];
    {
        int t = threadIdx.x;
        for (int j = t; j < 32 * 16; j += blockDim.x) w0[j] = lw0[j];
        for (int j = t; j < 16; j += blockDim.x) b0s[j] = lb0[j];
        for (int j = t; j < 16 * 8; j += blockDim.x) w1[j] = lw1[j];
        for (int j = t; j < 8; j += blockDim.x) b1s[j] = lb1[j];
        for (int j = t; j < 8; j += blockDim.x) w2s[j] = lw2[j];
        if (t == 0) b2s[0] = lb2[0];
    }
    __syncthreads();

    int warp = (blockIdx.x * blockDim.x + threadIdx.x) >> 5;
    int lane = threadIdx.x & 31;
    if (warp >= n) return;
    int v = warp;
    int s0 = offsets[v], s1 = offsets[v + 1];

    float a0[1] = {}, a1[1] = {}, a2[1] = {}, a3[1] = {};
    const __half* __restrict__ base = hs + lane;

    gather_rows<1>(base, csr, s0, s1, a0, a1, a2, a3);

    float dv = dis[v];
    float hv = __half2float(hs[(size_t)v * 32 + lane]);
    float xf = dv * ((a0[0] + a1[0]) + (a2[0] + a3[0]) + hv) + b[lane];
    xf = xf > 0.0f ? xf : 0.0f;  // node feature `lane`

    // MLP layer 1: lanes 0..15 own output j = lane
    float y1 = (lane < 16) ? b0s[lane] : 0.0f;
#pragma unroll
    for (int k = 0; k < 32; k++) {
        float xk = __shfl_sync(0xffffffffu, xf, k);
        if (lane < 16) y1 += xk * w0[k * 16 + lane];
    }
    y1 = y1 > 0.0f ? y1 : 0.0f;

    // MLP layer 2: lanes 0..7 own output j = lane
    float y2 = (lane < 8) ? b1s[lane] : 0.0f;
#pragma unroll
    for (int k = 0; k < 16; k++) {
        float yk = __shfl_sync(0xffffffffu, y1, k);
        if (lane < 8) y2 += yk * w1[k * 8 + lane];
    }
    y2 = y2 > 0.0f ? y2 : 0.0f;

    // MLP layer 3: dot over 8 lanes + sigmoid
    float z = (lane < 8) ? y2 * w2s[lane] : 0.0f;
    z += __shfl_xor_sync(0xffffffffu, z, 4);
    z += __shfl_xor_sync(0xffffffffu, z, 2);
    z += __shfl_xor_sync(0xffffffffu, z, 1);
    if (lane == 0) s[v] = 1.0f / (1.0f + expf(-(z + b2s[0])));
}

__global__ void edge_score_kernel(const int* __restrict__ pe,
                                  const float* __restrict__ s,
                                  float* __restrict__ out, int ep) {
    int i = blockIdx.x * blockDim.x + threadIdx.x;
    if (i < ep) {
        int2 p = ((const int2*)pe)[i];
        out[i] = s[p.x] * s[p.y];
    }
}

// ---------------------------------------------------------------------------
extern "C" void kernel_launch(void* const* d_in, const int* in_sizes, int n_in,
                              void* d_out, int out_size) {
    const float* x   = (const float*)d_in[0];
    const int* ei    = (const int*)d_in[1];
    const int* pe    = (const int*)d_in[2];
    const float* cw0 = (const float*)d_in[3];
    const float* cb0 = (const float*)d_in[4];
    const float* cw1 = (const float*)d_in[5];
    const float* cb1 = (const float*)d_in[6];
    const float* cw2 = (const float*)d_in[7];
    const float* cb2 = (const float*)d_in[8];
    const float* lw0 = (const float*)d_in[9];
    const float* lb0 = (const float*)d_in[10];
    const float* lw1 = (const float*)d_in[11];
    const float* lb1 = (const float*)d_in[12];
    const float* lw2 = (const float*)d_in[13];
    const float* lb2 = (const float*)d_in[14];
    float* out = (float*)d_out;

    const int N  = in_sizes[0] / 128;
    const int E  = in_sizes[1] / 2;
    const int EP = out_size;

    const int* src = ei;
    const int* dst = ei + E;

    float *dis, *sc;
    __half *hs, *xb;
    int *counts, *offsets, *cursor, *csr;
    cudaGetSymbolAddress((void**)&hs, g_hs);
    cudaGetSymbolAddress((void**)&xb, g_xh);
    cudaGetSymbolAddress((void**)&dis, g_dis);
    cudaGetSymbolAddress((void**)&sc, g_s);
    cudaGetSymbolAddress((void**)&counts, g_counts);
    cudaGetSymbolAddress((void**)&offsets, g_offsets);
    cudaGetSymbolAddress((void**)&cursor, g_cursor);
    cudaGetSymbolAddress((void**)&csr, g_csr);

    // Lazy side-stream + events for capture-legal fork/join.
    static cudaStream_t s_side = nullptr;
    static cudaEvent_t ev_fork = nullptr, ev_dis = nullptr, ev_join = nullptr;
    if (!s_side) {
        cudaStreamCreateWithFlags(&s_side, cudaStreamNonBlocking);
        cudaEventCreateWithFlags(&ev_fork, cudaEventDisableTiming);
        cudaEventCreateWithFlags(&ev_dis, cudaEventDisableTiming);
        cudaEventCreateWithFlags(&ev_join, cudaEventDisableTiming);
    }

    const int B = 256;
    const int E4 = (E + 3) / 4;
    int gwarp = (N * 32 + B - 1) / B;   // 1 warp per node
    int gemmb = (N + 63) / 64;          // BM=64 rows per block

    // ---- fork: CSR build + dis on side stream ----
    cudaEventRecord(ev_fork, 0);
    cudaStreamWaitEvent(s_side, ev_fork, 0);

    cudaMemsetAsync(counts, 0, N * sizeof(int), s_side);
    hist_kernel<<<(E4 + B - 1) / B, B, 0, s_side>>>(dst, E, counts);
    scan_fused_kernel<<<1, 1024, 0, s_side>>>(counts, offsets, cursor, dis, N);
    cudaEventRecord(ev_dis, s_side);   // dis/offsets ready
    fill_kernel<<<(E4 + B - 1) / B, B, 0, s_side>>>(src, dst, E, cursor, csr);
    cudaEventRecord(ev_join, s_side);  // csr ready

    // GEMM0 needs dis only (overlaps fill on the side stream)
    cudaStreamWaitEvent(0, ev_dis, 0);
    wmma_gemm_kernel<128, 128, float><<<gemmb, 256>>>(x, cw0, dis, hs, N);
    cudaStreamWaitEvent(0, ev_join, 0);
    // ---- join ----

    // Layer 0
    gather_combine_kernel<128><<<gwarp, B>>>(hs, csr, offsets, cb0, dis, xb, N);
    // Layer 1: 128 -> 64
    wmma_gemm_kernel<128, 64, __half><<<gemmb, 256>>>(xb, cw1, dis, hs, N);
    gather_combine_kernel<64><<<gwarp, B>>>(hs, csr, offsets, cb1, dis, xb, N);
    // Layer 2: 64 -> 32, gather fused with MLP head -> node scores
    wmma_gemm_kernel<64, 32, __half><<<gemmb, 256>>>(xb, cw2, dis, hs, N);
    gather_combine_mlp_kernel<<<gwarp, B>>>(hs, csr, offsets, cb2, dis,
                                            lw0, lb0, lw1, lb1, lw2, lb2, sc, N);

    edge_score_kernel<<<(EP + B - 1) / B, B>>>(pe, sc, out, EP);
}